// round 16
// baseline (speedup 1.0000x reference)
#include <cuda_runtime.h>
#include <cuda_bf16.h>
#include <cstdint>

#define BSZ   512
#define NNODE 22
#define INDIM 128
#define HID   256

// Scratch (device globals) — activations & weights pre-split (bf16 hi/lo)
__device__ __nv_bfloat16 g_hsh[BSZ * HID], g_hsl[BSZ * HID];
__device__ __nv_bfloat16 g_th [BSZ * HID], g_tl [BSZ * HID];
__device__ __nv_bfloat16 g_Wth[2 * HID * HID], g_Wtl[2 * HID * HID]; // [n][k]: W01, Wn2
__device__ float g_b01[HID];            // fused bias: 22*be2@Wn1 + bn1

// per-row-group counters for the tail's single sync; zeroed by K1 each replay
__device__ unsigned g_cnt[32];

// ---------------------------------------------------------------------------
// bf16 split-2 helpers
// ---------------------------------------------------------------------------
__device__ __forceinline__ void bf16_split2(float v0, float v1,
                                            uint32_t& hi, uint32_t& lo) {
    __nv_bfloat162 h = __float22bfloat162_rn(make_float2(v0, v1));
    float2 hf = __bfloat1622float2(h);
    __nv_bfloat162 l = __float22bfloat162_rn(make_float2(v0 - hf.x, v1 - hf.y));
    hi = *reinterpret_cast<uint32_t*>(&h);
    lo = *reinterpret_cast<uint32_t*>(&l);
}

__device__ __forceinline__ void split1(float v, __nv_bfloat16& h, __nv_bfloat16& l) {
    h = __float2bfloat16_rn(v);
    l = __float2bfloat16_rn(v - __bfloat162float(h));
}

__device__ __forceinline__ void mma_bf16(float* d, const uint32_t* a,
                                         uint32_t b0, uint32_t b1) {
    asm volatile(
        "mma.sync.aligned.m16n8k16.row.col.f32.bf16.bf16.f32 "
        "{%0,%1,%2,%3}, {%4,%5,%6,%7}, {%8,%9}, {%0,%1,%2,%3};"
        : "+f"(d[0]), "+f"(d[1]), "+f"(d[2]), "+f"(d[3])
        : "r"(a[0]), "r"(a[1]), "r"(a[2]), "r"(a[3]), "r"(b0), "r"(b1));
}

__device__ __forceinline__ uint32_t lds_u32(const __nv_bfloat16* p) {
    return *reinterpret_cast<const uint32_t*>(p);
}

// ---------------------------------------------------------------------------
// K1: main role (y<64): h = relu(x @ (We1[:128]+We1[128:]) + be1) + 22-row
// segment reduce -> split hs.
// Prep roles: y==64: Wn2 transpose+split (+counter reset);
//             y in 65..68: W01 = We2@Wn1 (fp32, MLP-8), 16 rows per block.
// grid (4, 69) = 276 blocks; __launch_bounds__(256,2) -> 2 blocks/SM ->
// capacity 296 >= 276 -> SINGLE WAVE.
// ---------------------------------------------------------------------------
__global__ void __launch_bounds__(256, 2)
k1_mma(const float* __restrict__ x,
       const float* __restrict__ We1,
       const float* __restrict__ be1,
       const float* __restrict__ We2,
       const float* __restrict__ be2,
       const float* __restrict__ Wn1,
       const float* __restrict__ bn1,
       const float* __restrict__ Wn2) {
    __shared__ __align__(16) unsigned char sm[176 * 68 * 4];

    const int t = threadIdx.x;

    if (blockIdx.y >= 64) {
        if (blockIdx.y == 64) {
            // ---- Wn2 transpose + split into slot 1 (+ counter reset) ----
            if (blockIdx.x == 0 && t < 32) g_cnt[t] = 0u;
            __nv_bfloat16* dh = g_Wth + HID * HID;
            __nv_bfloat16* dl = g_Wtl + HID * HID;
            const int k0 = blockIdx.x * 64;
            for (int kq = 0; kq < 64; kq += 4) {
                __nv_bfloat16 h[4], l[4];
#pragma unroll
                for (int i = 0; i < 4; i++)
                    split1(Wn2[(size_t)(k0 + kq + i) * HID + t], h[i], l[i]);
                *(uint2*)&dh[(size_t)t * HID + k0 + kq] = *(uint2*)h;
                *(uint2*)&dl[(size_t)t * HID + k0 + kq] = *(uint2*)l;
            }
            return;
        }
        // ---- W01 = We2 @ Wn1 (fp32), 16 rows per block; p in 0..15 ----
        const int p  = (blockIdx.y - 65) * 4 + blockIdx.x;
        const int r0 = p * 16;                 // k-rows r0..r0+15
        float* sW  = (float*)sm;               // [256 j][16 kk]
        float* sbe = (float*)(sm + 16384);     // be2 stage

        // stage We2 rows r0..r0+15 transposed (coalesced LDG per kk)
#pragma unroll
        for (int kk = 0; kk < 16; kk++)
            sW[t * 16 + kk] = We2[(size_t)(r0 + kk) * HID + t];
        sbe[t] = be2[t];
        __syncthreads();

        float acc[16], accb = 0.f;
#pragma unroll
        for (int kk = 0; kk < 16; kk++) acc[kk] = 0.f;

        for (int j0 = 0; j0 < HID; j0 += 8) {
            float w[8];
#pragma unroll
            for (int u = 0; u < 8; u++)                 // 8 independent LDGs
                w[u] = Wn1[(size_t)(j0 + u) * HID + t];
#pragma unroll
            for (int u = 0; u < 8; u++) {
                const float* a = &sW[(j0 + u) * 16];    // smem broadcast
#pragma unroll
                for (int kk = 0; kk < 16; kk++)
                    acc[kk] = fmaf(a[kk], w[u], acc[kk]);
                accb = fmaf(sbe[j0 + u], w[u], accb);
            }
        }

        // write transposed split: g_Wth[n][k], slot 0 (rows r0..r0+15)
#pragma unroll
        for (int q = 0; q < 4; q++) {
            __nv_bfloat16 h[4], l[4];
#pragma unroll
            for (int i = 0; i < 4; i++) split1(acc[q * 4 + i], h[i], l[i]);
            *(uint2*)&g_Wth[(size_t)t * HID + r0 + q * 4] = *(uint2*)h;
            *(uint2*)&g_Wtl[(size_t)t * HID + r0 + q * 4] = *(uint2*)l;
        }
        if (p == 0) g_b01[t] = fmaf((float)NNODE, accb, bn1[t]);
        return;
    }

    // ======== main K1 (round-7 body) ========
    __nv_bfloat16* Ah = (__nv_bfloat16*)sm;                    // [176][40]
    __nv_bfloat16* Al = (__nv_bfloat16*)(sm + 14080);
    __nv_bfloat16* Bh = (__nv_bfloat16*)(sm + 28160);          // [64][40]
    __nv_bfloat16* Bl = (__nv_bfloat16*)(sm + 33280);
    float* hb = (float*)sm;                                    // [176][68]

    const int w  = t >> 5;
    const int l  = t & 31;
    const int g  = l >> 2;
    const int t4 = l & 3;
    const int n0 = blockIdx.x * 64;
    const int m0 = blockIdx.y * 176;

    float acc[11][4];
#pragma unroll
    for (int mt = 0; mt < 11; mt++)
#pragma unroll
        for (int j = 0; j < 4; j++) acc[mt][j] = 0.0f;

    for (int kc = 0; kc < 4; kc++) {
        const int k0 = kc * 32;
#pragma unroll
        for (int j = 0; j < 6; j++) {
            int flat = j * 256 + t;
            if (flat < 1408) {
                int m  = flat >> 3;
                int kq = (flat & 7) * 4;
                float4 v = *(const float4*)&x[(size_t)(m0 + m) * INDIM + k0 + kq];
                uint32_t h0, l0, h1, l1;
                bf16_split2(v.x, v.y, h0, l0);
                bf16_split2(v.z, v.w, h1, l1);
                *(uint32_t*)&Ah[m * 40 + kq]     = h0;
                *(uint32_t*)&Ah[m * 40 + kq + 2] = h1;
                *(uint32_t*)&Al[m * 40 + kq]     = l0;
                *(uint32_t*)&Al[m * 40 + kq + 2] = l1;
            }
        }
#pragma unroll
        for (int j = 0; j < 8; j++) {
            int flat = j * 256 + t;
            int kl = flat >> 6;
            int n  = flat & 63;
            float v = We1[(size_t)(k0 + kl) * HID + n0 + n]
                    + We1[(size_t)(k0 + kl + INDIM) * HID + n0 + n];
            split1(v, Bh[n * 40 + kl], Bl[n * 40 + kl]);
        }
        __syncthreads();

#pragma unroll
        for (int ks = 0; ks < 2; ks++) {
            const int kb = ks * 16 + 2 * t4;
            uint32_t bh0 = lds_u32(Bh + (8 * w + g) * 40 + kb);
            uint32_t bh1 = lds_u32(Bh + (8 * w + g) * 40 + kb + 8);
            uint32_t bl0 = lds_u32(Bl + (8 * w + g) * 40 + kb);
            uint32_t bl1 = lds_u32(Bl + (8 * w + g) * 40 + kb + 8);
#pragma unroll
            for (int mt = 0; mt < 11; mt++) {
                const int rb = mt * 16;
                uint32_t ah[4], al[4];
                ah[0] = lds_u32(Ah + (rb + g) * 40 + kb);
                ah[1] = lds_u32(Ah + (rb + g + 8) * 40 + kb);
                ah[2] = lds_u32(Ah + (rb + g) * 40 + kb + 8);
                ah[3] = lds_u32(Ah + (rb + g + 8) * 40 + kb + 8);
                al[0] = lds_u32(Al + (rb + g) * 40 + kb);
                al[1] = lds_u32(Al + (rb + g + 8) * 40 + kb);
                al[2] = lds_u32(Al + (rb + g) * 40 + kb + 8);
                al[3] = lds_u32(Al + (rb + g + 8) * 40 + kb + 8);
                mma_bf16(acc[mt], ah, bh0, bh1);
                mma_bf16(acc[mt], ah, bl0, bl1);
                mma_bf16(acc[mt], al, bh0, bh1);
            }
        }
        __syncthreads();
    }

    const int   cc  = 8 * w + 2 * t4;
    const float bv0 = be1[n0 + cc];
    const float bv1 = be1[n0 + cc + 1];
#pragma unroll
    for (int mt = 0; mt < 11; mt++) {
        const int r0 = mt * 16 + g;
        const int r1 = r0 + 8;
        hb[r0 * 68 + cc]     = fmaxf(acc[mt][0] + bv0, 0.0f);
        hb[r0 * 68 + cc + 1] = fmaxf(acc[mt][1] + bv1, 0.0f);
        hb[r1 * 68 + cc]     = fmaxf(acc[mt][2] + bv0, 0.0f);
        hb[r1 * 68 + cc + 1] = fmaxf(acc[mt][3] + bv1, 0.0f);
    }
    __syncthreads();

    {
        const int c = t & 63;
#pragma unroll
        for (int hh = 0; hh < 2; hh++) {
            const int gg = (t >> 6) + hh * 4;
            float s = 0.0f;
#pragma unroll
            for (int i = 0; i < 22; i++)
                s += hb[(gg * 22 + i) * 68 + c];
            size_t o = (size_t)(blockIdx.y * 8 + gg) * HID + n0 + c;
            split1(s, g_hsh[o], g_hsl[o]);
        }
    }
}

// ---------------------------------------------------------------------------
// Tail layer (round-11 verified body): 16 rows x 32 cols, 128 threads,
// warp split-K (64 each) + smem reduce.
// ---------------------------------------------------------------------------
template <bool RELU, bool BCAST>
__device__ __forceinline__ void tail_layer(
    unsigned char* sm,
    const __nv_bfloat16* __restrict__ Ahg, const __nv_bfloat16* __restrict__ Alg,
    const __nv_bfloat16* __restrict__ Wh,  const __nv_bfloat16* __restrict__ Wl,
    const float* __restrict__ bias, float biasScale,
    float* __restrict__ Cf,
    __nv_bfloat16* __restrict__ Chg, __nv_bfloat16* __restrict__ Clg,
    int m0, int n0) {
    __nv_bfloat16* Ah = (__nv_bfloat16*)sm;             // [16][256]
    __nv_bfloat16* Al = (__nv_bfloat16*)(sm + 8192);
    __nv_bfloat16* Bh = (__nv_bfloat16*)(sm + 16384);   // [32][256]
    __nv_bfloat16* Bl = (__nv_bfloat16*)(sm + 32768);
    typedef float RedT[16][33];
    RedT* red = (RedT*)(sm + 16384);                    // alias Bh (post-sync)

    const int t  = threadIdx.x;
    const int w  = t >> 5;
    const int l  = t & 31;
    const int g  = l >> 2;
    const int t4 = l & 3;

#pragma unroll
    for (int j = 0; j < 4; j++) {
        int flat = j * 128 + t;            // uint4 index over [16][32]
        int m   = flat >> 5;
        int kq8 = (flat & 31) * 8;
        int kx  = kq8 ^ (8 * (m & 7));
        *(uint4*)&Ah[m * 256 + kx] = *(const uint4*)&Ahg[(size_t)(m0 + m) * HID + kq8];
        *(uint4*)&Al[m * 256 + kx] = *(const uint4*)&Alg[(size_t)(m0 + m) * HID + kq8];
    }
#pragma unroll
    for (int j = 0; j < 8; j++) {
        int flat = j * 128 + t;            // uint4 index over [32][32]
        int n   = flat >> 5;
        int kq8 = (flat & 31) * 8;
        int kx  = kq8 ^ (8 * (n & 7));
        *(uint4*)&Bh[n * 256 + kx] = *(const uint4*)&Wh[(size_t)(n0 + n) * HID + kq8];
        *(uint4*)&Bl[n * 256 + kx] = *(const uint4*)&Wl[(size_t)(n0 + n) * HID + kq8];
    }
    __syncthreads();

    float acc[4][4];
#pragma unroll
    for (int nt = 0; nt < 4; nt++)
#pragma unroll
        for (int j = 0; j < 4; j++) acc[nt][j] = 0.0f;

#pragma unroll
    for (int ks = 0; ks < 4; ks++) {
        const int kb  = 64 * w + 16 * ks;
        const int ka0 = (kb + 2 * t4) ^ (8 * g);
        const int ka2 = (kb + 2 * t4 + 8) ^ (8 * g);

        uint32_t ah[4], al[4];
        ah[0] = lds_u32(Ah + g * 256 + ka0);
        ah[1] = lds_u32(Ah + (g + 8) * 256 + ka0);
        ah[2] = lds_u32(Ah + g * 256 + ka2);
        ah[3] = lds_u32(Ah + (g + 8) * 256 + ka2);
        al[0] = lds_u32(Al + g * 256 + ka0);
        al[1] = lds_u32(Al + (g + 8) * 256 + ka0);
        al[2] = lds_u32(Al + g * 256 + ka2);
        al[3] = lds_u32(Al + (g + 8) * 256 + ka2);

#pragma unroll
        for (int nt = 0; nt < 4; nt++) {
            const int n = nt * 8 + g;
            uint32_t bh0 = lds_u32(Bh + n * 256 + ka0);
            uint32_t bh1 = lds_u32(Bh + n * 256 + ka2);
            uint32_t bl0 = lds_u32(Bl + n * 256 + ka0);
            uint32_t bl1 = lds_u32(Bl + n * 256 + ka2);
            mma_bf16(acc[nt], ah, bh0, bh1);
            mma_bf16(acc[nt], ah, bl0, bl1);
            mma_bf16(acc[nt], al, bh0, bh1);
        }
    }
    __syncthreads();

#pragma unroll
    for (int nt = 0; nt < 4; nt++) {
        const int col = nt * 8 + 2 * t4;
        red[w][g][col]         = acc[nt][0];
        red[w][g][col + 1]     = acc[nt][1];
        red[w][g + 8][col]     = acc[nt][2];
        red[w][g + 8][col + 1] = acc[nt][3];
    }
    __syncthreads();

    const int row = t >> 3;
    const int cb  = (t & 7) * 4;
    float v[4];
#pragma unroll
    for (int j = 0; j < 4; j++)
        v[j] = red[0][row][cb + j] + red[1][row][cb + j]
             + red[2][row][cb + j] + red[3][row][cb + j];

    const float4 bv = *(const float4*)&bias[n0 + cb];
    float o[4];
    o[0] = v[0] + biasScale * bv.x;
    o[1] = v[1] + biasScale * bv.y;
    o[2] = v[2] + biasScale * bv.z;
    o[3] = v[3] + biasScale * bv.w;
    if (RELU) {
#pragma unroll
        for (int j = 0; j < 4; j++) o[j] = fmaxf(o[j], 0.0f);
    }

    const int rowg = m0 + row;
    const int colg = n0 + cb;
    if (!BCAST) {
        __nv_bfloat16 h[4], lo[4];
#pragma unroll
        for (int j = 0; j < 4; j++) split1(o[j], h[j], lo[j]);
        *(uint2*)&Chg[(size_t)rowg * HID + colg] = *(uint2*)h;
        *(uint2*)&Clg[(size_t)rowg * HID + colg] = *(uint2*)lo;
    } else {
        float4 ov = make_float4(o[0], o[1], o[2], o[3]);
        size_t base = ((size_t)rowg * NNODE) * HID + colg;
#pragma unroll
        for (int p = 0; p < NNODE; p++)
            *(float4*)&Cf[base + (size_t)p * HID] = ov;
    }
}

// ---------------------------------------------------------------------------
// Row-group dataflow sync (counters pre-zeroed by K1; kernel-boundary ordered).
// All 256 blocks co-resident (48KB smem, 128 thr) -> no deadlock.
// ---------------------------------------------------------------------------
__device__ __forceinline__ void row_sync(int mg) {
    __threadfence();
    __syncthreads();
    if (threadIdx.x == 0) {
        atomicAdd(&g_cnt[mg], 1u);
        volatile unsigned* c = &g_cnt[mg];
        while (*c < 8u) { }
        __threadfence();
    }
    __syncthreads();
}

// ---------------------------------------------------------------------------
// Fused 2-layer tail: t = relu(hs@W01 + b01); out = t@Wn2 + bn2 (bcast).
// grid 256 (bx&7 = n-tile, bx>>3 = m-group), 128 threads, 48KB smem.
// ---------------------------------------------------------------------------
__global__ __launch_bounds__(128)
void tail2(const float* __restrict__ bn2, float* __restrict__ out) {
    __shared__ __align__(16) unsigned char sm[49152];

    const int n0 = (blockIdx.x & 7) * 32;
    const int mg = blockIdx.x >> 3;
    const int m0 = mg * 16;

    // L1': t = relu(hs @ W01 + b01)
    tail_layer<true, false>(sm, g_hsh, g_hsl, g_Wth, g_Wtl,
                            g_b01, 1.0f, nullptr, g_th, g_tl, m0, n0);
    row_sync(mg);
    // L2: out = t @ Wn2 + bn2, broadcast over 22 nodes
    tail_layer<false, true>(sm, g_th, g_tl,
                            g_Wth + HID * HID, g_Wtl + HID * HID,
                            bn2, 1.0f, out, nullptr, nullptr, m0, n0);
}

// ---------------------------------------------------------------------------
extern "C" void kernel_launch(void* const* d_in, const int* in_sizes, int n_in,
                              void* d_out, int out_size) {
    const float* x   = (const float*)d_in[0];
    const float* We1 = (const float*)d_in[1];
    const float* be1 = (const float*)d_in[2];
    const float* We2 = (const float*)d_in[3];
    const float* be2 = (const float*)d_in[4];
    const float* Wn1 = (const float*)d_in[5];
    const float* bn1 = (const float*)d_in[6];
    const float* Wn2 = (const float*)d_in[7];
    const float* bn2 = (const float*)d_in[8];
    float* out = (float*)d_out;

    // K1 main + prep (Wn2 split, W01 = We2@Wn1 MLP-8 x16 blocks, b01,
    // counter reset) — single wave at 2 blocks/SM
    k1_mma<<<dim3(4, 69), 256>>>(x, We1, be1, We2, be2, Wn1, bn1, Wn2);

    // Fused 2-layer tail with one row-group sync
    tail2<<<256, 128>>>(bn2, out);
}

// round 17
// speedup vs baseline: 1.1169x; 1.1169x over previous
#include <cuda_runtime.h>
#include <cuda_bf16.h>
#include <cstdint>

#define BSZ   512
#define NNODE 22
#define INDIM 128
#define HID   256

// Scratch (device globals) — activations & weights pre-split (bf16 hi/lo)
__device__ __nv_bfloat16 g_hsh[BSZ * HID], g_hsl[BSZ * HID];
__device__ __nv_bfloat16 g_th [BSZ * HID], g_tl [BSZ * HID];
__device__ __nv_bfloat16 g_Wth[2 * HID * HID], g_Wtl[2 * HID * HID]; // [n][k]: W01, Wn2
__device__ float g_b01[HID];            // fused bias: 22*be2@Wn1 + bn1

// per-row-group counters for the tail's single sync; zeroed by K1 each replay
__device__ unsigned g_cnt[32];

// ---------------------------------------------------------------------------
// bf16 split-2 helpers
// ---------------------------------------------------------------------------
__device__ __forceinline__ void bf16_split2(float v0, float v1,
                                            uint32_t& hi, uint32_t& lo) {
    __nv_bfloat162 h = __float22bfloat162_rn(make_float2(v0, v1));
    float2 hf = __bfloat1622float2(h);
    __nv_bfloat162 l = __float22bfloat162_rn(make_float2(v0 - hf.x, v1 - hf.y));
    hi = *reinterpret_cast<uint32_t*>(&h);
    lo = *reinterpret_cast<uint32_t*>(&l);
}

__device__ __forceinline__ void split1(float v, __nv_bfloat16& h, __nv_bfloat16& l) {
    h = __float2bfloat16_rn(v);
    l = __float2bfloat16_rn(v - __bfloat162float(h));
}

__device__ __forceinline__ void mma_bf16(float* d, const uint32_t* a,
                                         uint32_t b0, uint32_t b1) {
    asm volatile(
        "mma.sync.aligned.m16n8k16.row.col.f32.bf16.bf16.f32 "
        "{%0,%1,%2,%3}, {%4,%5,%6,%7}, {%8,%9}, {%0,%1,%2,%3};"
        : "+f"(d[0]), "+f"(d[1]), "+f"(d[2]), "+f"(d[3])
        : "r"(a[0]), "r"(a[1]), "r"(a[2]), "r"(a[3]), "r"(b0), "r"(b1));
}

__device__ __forceinline__ uint32_t lds_u32(const __nv_bfloat16* p) {
    return *reinterpret_cast<const uint32_t*>(p);
}

// ---------------------------------------------------------------------------
// K1, single-wave edition: grid = 148 blocks x 256 threads, ~93KB dyn smem
// (1 block/SM by smem; 148 <= 148 SMs -> exactly one wave).
//  b in [0,128): main K1, BM=176 (8 groups of 22), BN=128; cx=b>>6, cy=b&63.
//  b in [128,144): W01 = We2@Wn1 (fp32, MLP-8), 16 rows per block.
//  b in [144,148): Wn2 transpose+split (b==144 also resets tail counters).
// ---------------------------------------------------------------------------
__global__ void k1_mma(const float* __restrict__ x,
                       const float* __restrict__ We1,
                       const float* __restrict__ be1,
                       const float* __restrict__ We2,
                       const float* __restrict__ be2,
                       const float* __restrict__ Wn1,
                       const float* __restrict__ bn1,
                       const float* __restrict__ Wn2) {
    extern __shared__ __align__(16) unsigned char sm[];

    const int b = blockIdx.x;
    const int t = threadIdx.x;

    if (b >= 128) {
        if (b >= 144) {
            // ---- Wn2 transpose + split into slot 1 (+ counter reset) ----
            if (b == 144 && t < 32) g_cnt[t] = 0u;
            __nv_bfloat16* dh = g_Wth + HID * HID;
            __nv_bfloat16* dl = g_Wtl + HID * HID;
            const int k0 = (b - 144) * 64;
            for (int kq = 0; kq < 64; kq += 4) {
                __nv_bfloat16 h[4], l[4];
#pragma unroll
                for (int i = 0; i < 4; i++)
                    split1(Wn2[(size_t)(k0 + kq + i) * HID + t], h[i], l[i]);
                *(uint2*)&dh[(size_t)t * HID + k0 + kq] = *(uint2*)h;
                *(uint2*)&dl[(size_t)t * HID + k0 + kq] = *(uint2*)l;
            }
            return;
        }
        // ---- W01 = We2 @ Wn1 (fp32), 16 rows per block; p in 0..15 ----
        const int p  = b - 128;
        const int r0 = p * 16;
        float* sW  = (float*)sm;               // [256 j][16 kk]
        float* sbe = (float*)(sm + 16384);     // be2 stage

#pragma unroll
        for (int kk = 0; kk < 16; kk++)
            sW[t * 16 + kk] = We2[(size_t)(r0 + kk) * HID + t];
        sbe[t] = be2[t];
        __syncthreads();

        float acc[16], accb = 0.f;
#pragma unroll
        for (int kk = 0; kk < 16; kk++) acc[kk] = 0.f;

        for (int j0 = 0; j0 < HID; j0 += 8) {
            float w[8];
#pragma unroll
            for (int u = 0; u < 8; u++)                 // 8 independent LDGs
                w[u] = Wn1[(size_t)(j0 + u) * HID + t];
#pragma unroll
            for (int u = 0; u < 8; u++) {
                const float* a = &sW[(j0 + u) * 16];    // smem broadcast
#pragma unroll
                for (int kk = 0; kk < 16; kk++)
                    acc[kk] = fmaf(a[kk], w[u], acc[kk]);
                accb = fmaf(sbe[j0 + u], w[u], accb);
            }
        }

#pragma unroll
        for (int q = 0; q < 4; q++) {
            __nv_bfloat16 h[4], l[4];
#pragma unroll
            for (int i = 0; i < 4; i++) split1(acc[q * 4 + i], h[i], l[i]);
            *(uint2*)&g_Wth[(size_t)t * HID + r0 + q * 4] = *(uint2*)h;
            *(uint2*)&g_Wtl[(size_t)t * HID + r0 + q * 4] = *(uint2*)l;
        }
        if (p == 0) g_b01[t] = fmaf((float)NNODE, accb, bn1[t]);
        return;
    }

    // ======== main K1: BM=176, BN=128 (validated in R13) ========
    __nv_bfloat16* Ah = (__nv_bfloat16*)sm;               // [176][40]
    __nv_bfloat16* Al = (__nv_bfloat16*)(sm + 14080);
    __nv_bfloat16* Bh = (__nv_bfloat16*)(sm + 28160);     // [128][40]
    __nv_bfloat16* Bl = (__nv_bfloat16*)(sm + 38400);     // end 48640
    float* hb = (float*)sm;                               // [176][132] (post-sync alias)

    const int w  = t >> 5;
    const int l  = t & 31;
    const int g  = l >> 2;
    const int t4 = l & 3;
    const int cx = b >> 6;            // 0..1
    const int cy = b & 63;            // 0..63
    const int n0 = cx * 128;
    const int m0 = cy * 176;

    float acc[11][2][4];
#pragma unroll
    for (int mt = 0; mt < 11; mt++)
#pragma unroll
        for (int u = 0; u < 2; u++)
#pragma unroll
            for (int j = 0; j < 4; j++) acc[mt][u][j] = 0.0f;

    for (int kc = 0; kc < 4; kc++) {
        const int k0 = kc * 32;
        // stage A [176 x 32] hi/lo (stride 40)
#pragma unroll
        for (int j = 0; j < 6; j++) {
            int flat = j * 256 + t;
            if (flat < 1408) {
                int m  = flat >> 3;
                int kq = (flat & 7) * 4;
                float4 v = *(const float4*)&x[(size_t)(m0 + m) * INDIM + k0 + kq];
                uint32_t h0, l0, h1, l1;
                bf16_split2(v.x, v.y, h0, l0);
                bf16_split2(v.z, v.w, h1, l1);
                *(uint32_t*)&Ah[m * 40 + kq]     = h0;
                *(uint32_t*)&Ah[m * 40 + kq + 2] = h1;
                *(uint32_t*)&Al[m * 40 + kq]     = l0;
                *(uint32_t*)&Al[m * 40 + kq + 2] = l1;
            }
        }
        // stage B^T [128 n x 32 k] with inline We1 fold
#pragma unroll
        for (int j = 0; j < 16; j++) {
            int flat = j * 256 + t;
            int kl = flat >> 7;       // 0..31
            int n  = flat & 127;
            float v = We1[(size_t)(k0 + kl) * HID + n0 + n]
                    + We1[(size_t)(k0 + kl + INDIM) * HID + n0 + n];
            split1(v, Bh[n * 40 + kl], Bl[n * 40 + kl]);
        }
        __syncthreads();

#pragma unroll
        for (int ks = 0; ks < 2; ks++) {
            const int kb = ks * 16 + 2 * t4;
            uint32_t bh0[2], bh1[2], bl0[2], bl1[2];
#pragma unroll
            for (int u = 0; u < 2; u++) {
                const int n = 16 * w + 8 * u + g;
                bh0[u] = lds_u32(Bh + n * 40 + kb);
                bh1[u] = lds_u32(Bh + n * 40 + kb + 8);
                bl0[u] = lds_u32(Bl + n * 40 + kb);
                bl1[u] = lds_u32(Bl + n * 40 + kb + 8);
            }
#pragma unroll
            for (int mt = 0; mt < 11; mt++) {
                const int rb = mt * 16;
                uint32_t ah[4], al[4];
                ah[0] = lds_u32(Ah + (rb + g) * 40 + kb);
                ah[1] = lds_u32(Ah + (rb + g + 8) * 40 + kb);
                ah[2] = lds_u32(Ah + (rb + g) * 40 + kb + 8);
                ah[3] = lds_u32(Ah + (rb + g + 8) * 40 + kb + 8);
                al[0] = lds_u32(Al + (rb + g) * 40 + kb);
                al[1] = lds_u32(Al + (rb + g + 8) * 40 + kb);
                al[2] = lds_u32(Al + (rb + g) * 40 + kb + 8);
                al[3] = lds_u32(Al + (rb + g + 8) * 40 + kb + 8);
#pragma unroll
                for (int u = 0; u < 2; u++) {
                    mma_bf16(acc[mt][u], ah, bh0[u], bh1[u]);
                    mma_bf16(acc[mt][u], ah, bl0[u], bl1[u]);
                    mma_bf16(acc[mt][u], al, bh0[u], bh1[u]);
                }
            }
        }
        __syncthreads();
    }

    // epilogue: relu(acc + bias) -> hb [176][132]
#pragma unroll
    for (int u = 0; u < 2; u++) {
        const int   cc  = 16 * w + 8 * u + 2 * t4;
        const float bv0 = be1[n0 + cc];
        const float bv1 = be1[n0 + cc + 1];
#pragma unroll
        for (int mt = 0; mt < 11; mt++) {
            const int r0 = mt * 16 + g;
            const int r1 = r0 + 8;
            hb[r0 * 132 + cc]     = fmaxf(acc[mt][u][0] + bv0, 0.0f);
            hb[r0 * 132 + cc + 1] = fmaxf(acc[mt][u][1] + bv1, 0.0f);
            hb[r1 * 132 + cc]     = fmaxf(acc[mt][u][2] + bv0, 0.0f);
            hb[r1 * 132 + cc + 1] = fmaxf(acc[mt][u][3] + bv1, 0.0f);
        }
    }
    __syncthreads();

    // 22-row segment reduce: 8 groups x 128 cols, 4 outputs/thread
    {
        const int c = t & 127;
#pragma unroll
        for (int hh = 0; hh < 4; hh++) {
            const int gg = (t >> 7) + hh * 2;   // 0..7
            float s = 0.0f;
#pragma unroll
            for (int i = 0; i < 22; i++)
                s += hb[(gg * 22 + i) * 132 + c];
            size_t o = (size_t)(cy * 8 + gg) * HID + n0 + c;
            split1(s, g_hsh[o], g_hsl[o]);
        }
    }
}

// ---------------------------------------------------------------------------
// Tail layer (round-11 verified body): 16 rows x 32 cols, 128 threads,
// warp split-K (64 each) + smem reduce.
// ---------------------------------------------------------------------------
template <bool RELU, bool BCAST>
__device__ __forceinline__ void tail_layer(
    unsigned char* sm,
    const __nv_bfloat16* __restrict__ Ahg, const __nv_bfloat16* __restrict__ Alg,
    const __nv_bfloat16* __restrict__ Wh,  const __nv_bfloat16* __restrict__ Wl,
    const float* __restrict__ bias, float biasScale,
    float* __restrict__ Cf,
    __nv_bfloat16* __restrict__ Chg, __nv_bfloat16* __restrict__ Clg,
    int m0, int n0) {
    __nv_bfloat16* Ah = (__nv_bfloat16*)sm;             // [16][256]
    __nv_bfloat16* Al = (__nv_bfloat16*)(sm + 8192);
    __nv_bfloat16* Bh = (__nv_bfloat16*)(sm + 16384);   // [32][256]
    __nv_bfloat16* Bl = (__nv_bfloat16*)(sm + 32768);
    typedef float RedT[16][33];
    RedT* red = (RedT*)(sm + 16384);                    // alias Bh (post-sync)

    const int t  = threadIdx.x;
    const int w  = t >> 5;
    const int l  = t & 31;
    const int g  = l >> 2;
    const int t4 = l & 3;

#pragma unroll
    for (int j = 0; j < 4; j++) {
        int flat = j * 128 + t;            // uint4 index over [16][32]
        int m   = flat >> 5;
        int kq8 = (flat & 31) * 8;
        int kx  = kq8 ^ (8 * (m & 7));
        *(uint4*)&Ah[m * 256 + kx] = *(const uint4*)&Ahg[(size_t)(m0 + m) * HID + kq8];
        *(uint4*)&Al[m * 256 + kx] = *(const uint4*)&Alg[(size_t)(m0 + m) * HID + kq8];
    }
#pragma unroll
    for (int j = 0; j < 8; j++) {
        int flat = j * 128 + t;            // uint4 index over [32][32]
        int n   = flat >> 5;
        int kq8 = (flat & 31) * 8;
        int kx  = kq8 ^ (8 * (n & 7));
        *(uint4*)&Bh[n * 256 + kx] = *(const uint4*)&Wh[(size_t)(n0 + n) * HID + kq8];
        *(uint4*)&Bl[n * 256 + kx] = *(const uint4*)&Wl[(size_t)(n0 + n) * HID + kq8];
    }
    __syncthreads();

    float acc[4][4];
#pragma unroll
    for (int nt = 0; nt < 4; nt++)
#pragma unroll
        for (int j = 0; j < 4; j++) acc[nt][j] = 0.0f;

#pragma unroll
    for (int ks = 0; ks < 4; ks++) {
        const int kb  = 64 * w + 16 * ks;
        const int ka0 = (kb + 2 * t4) ^ (8 * g);
        const int ka2 = (kb + 2 * t4 + 8) ^ (8 * g);

        uint32_t ah[4], al[4];
        ah[0] = lds_u32(Ah + g * 256 + ka0);
        ah[1] = lds_u32(Ah + (g + 8) * 256 + ka0);
        ah[2] = lds_u32(Ah + g * 256 + ka2);
        ah[3] = lds_u32(Ah + (g + 8) * 256 + ka2);
        al[0] = lds_u32(Al + g * 256 + ka0);
        al[1] = lds_u32(Al + (g + 8) * 256 + ka0);
        al[2] = lds_u32(Al + g * 256 + ka2);
        al[3] = lds_u32(Al + (g + 8) * 256 + ka2);

#pragma unroll
        for (int nt = 0; nt < 4; nt++) {
            const int n = nt * 8 + g;
            uint32_t bh0 = lds_u32(Bh + n * 256 + ka0);
            uint32_t bh1 = lds_u32(Bh + n * 256 + ka2);
            uint32_t bl0 = lds_u32(Bl + n * 256 + ka0);
            uint32_t bl1 = lds_u32(Bl + n * 256 + ka2);
            mma_bf16(acc[nt], ah, bh0, bh1);
            mma_bf16(acc[nt], ah, bl0, bl1);
            mma_bf16(acc[nt], al, bh0, bh1);
        }
    }
    __syncthreads();

#pragma unroll
    for (int nt = 0; nt < 4; nt++) {
        const int col = nt * 8 + 2 * t4;
        red[w][g][col]         = acc[nt][0];
        red[w][g][col + 1]     = acc[nt][1];
        red[w][g + 8][col]     = acc[nt][2];
        red[w][g + 8][col + 1] = acc[nt][3];
    }
    __syncthreads();

    const int row = t >> 3;
    const int cb  = (t & 7) * 4;
    float v[4];
#pragma unroll
    for (int j = 0; j < 4; j++)
        v[j] = red[0][row][cb + j] + red[1][row][cb + j]
             + red[2][row][cb + j] + red[3][row][cb + j];

    const float4 bv = *(const float4*)&bias[n0 + cb];
    float o[4];
    o[0] = v[0] + biasScale * bv.x;
    o[1] = v[1] + biasScale * bv.y;
    o[2] = v[2] + biasScale * bv.z;
    o[3] = v[3] + biasScale * bv.w;
    if (RELU) {
#pragma unroll
        for (int j = 0; j < 4; j++) o[j] = fmaxf(o[j], 0.0f);
    }

    const int rowg = m0 + row;
    const int colg = n0 + cb;
    if (!BCAST) {
        __nv_bfloat16 h[4], lo[4];
#pragma unroll
        for (int j = 0; j < 4; j++) split1(o[j], h[j], lo[j]);
        *(uint2*)&Chg[(size_t)rowg * HID + colg] = *(uint2*)h;
        *(uint2*)&Clg[(size_t)rowg * HID + colg] = *(uint2*)lo;
    } else {
        float4 ov = make_float4(o[0], o[1], o[2], o[3]);
        size_t base = ((size_t)rowg * NNODE) * HID + colg;
#pragma unroll
        for (int p = 0; p < NNODE; p++)
            *(float4*)&Cf[base + (size_t)p * HID] = ov;
    }
}

// ---------------------------------------------------------------------------
// Row-group dataflow sync (counters pre-zeroed by K1; kernel-boundary ordered).
// All 256 blocks co-resident (48KB smem, 128 thr, 3 blocks/SM) -> no deadlock.
// ---------------------------------------------------------------------------
__device__ __forceinline__ void row_sync(int mg) {
    __threadfence();
    __syncthreads();
    if (threadIdx.x == 0) {
        atomicAdd(&g_cnt[mg], 1u);
        volatile unsigned* c = &g_cnt[mg];
        while (*c < 8u) { }
        __threadfence();
    }
    __syncthreads();
}

// ---------------------------------------------------------------------------
// Fused 2-layer tail: t = relu(hs@W01 + b01); out = t@Wn2 + bn2 (bcast).
// grid 256 (bx&7 = n-tile, bx>>3 = m-group), 128 threads, 48KB smem.
// ---------------------------------------------------------------------------
__global__ __launch_bounds__(128)
void tail2(const float* __restrict__ bn2, float* __restrict__ out) {
    __shared__ __align__(16) unsigned char sm[49152];

    const int n0 = (blockIdx.x & 7) * 32;
    const int mg = blockIdx.x >> 3;
    const int m0 = mg * 16;

    // L1': t = relu(hs @ W01 + b01)
    tail_layer<true, false>(sm, g_hsh, g_hsl, g_Wth, g_Wtl,
                            g_b01, 1.0f, nullptr, g_th, g_tl, m0, n0);
    row_sync(mg);
    // L2: out = t @ Wn2 + bn2, broadcast over 22 nodes
    tail_layer<false, true>(sm, g_th, g_tl,
                            g_Wth + HID * HID, g_Wtl + HID * HID,
                            bn2, 1.0f, out, nullptr, nullptr, m0, n0);
}

// ---------------------------------------------------------------------------
extern "C" void kernel_launch(void* const* d_in, const int* in_sizes, int n_in,
                              void* d_out, int out_size) {
    const float* x   = (const float*)d_in[0];
    const float* We1 = (const float*)d_in[1];
    const float* be1 = (const float*)d_in[2];
    const float* We2 = (const float*)d_in[3];
    const float* be2 = (const float*)d_in[4];
    const float* Wn1 = (const float*)d_in[5];
    const float* bn1 = (const float*)d_in[6];
    const float* Wn2 = (const float*)d_in[7];
    const float* bn2 = (const float*)d_in[8];
    float* out = (float*)d_out;

    constexpr int DSMEM = 176 * 132 * 4;   // 92928 B (hb aliases staging)
    static int smem_set = 0;
    if (!smem_set) {
        cudaFuncSetAttribute(k1_mma,
                             cudaFuncAttributeMaxDynamicSharedMemorySize, DSMEM);
        smem_set = 1;
    }

    // K1 single-wave: 128 main + 16 W01-prep + 4 Wn2-split = 148 blocks
    k1_mma<<<148, 256, DSMEM>>>(x, We1, be1, We2, be2, Wn1, bn1, Wn2);

    // Fused 2-layer tail with one row-group sync
    tail2<<<256, 128>>>(bn2, out);
}